// round 9
// baseline (speedup 1.0000x reference)
#include <cuda_runtime.h>
#include <cuda_bf16.h>
#include <math.h>

#define Bz   2
#define Cc   512
#define Tt   16
#define HWp  1024
#define EPS  1e-5f
#define SCALE 0.04419417382415922f  // 512^-0.5
#define FULLMASK 0xffffffffu
#define HST2 68     // h chunk row stride (uints/pairs); 68%32=4 -> conflict-free A frags
#define KST2 72     // kT chunk row stride; 72%32=8 -> conflict-free B frags
#define VSTC 136    // v chunk row stride; 136%32=8
#define SSTR 68     // fp32 score row stride
#define WST  36     // packed weight row stride

typedef unsigned int uint;

// ---------------- helpers ----------------
__device__ __forceinline__ uint packbf(float lo, float hi) {
    uint r; asm("cvt.rn.bf16x2.f32 %0, %1, %2;" : "=r"(r) : "f"(hi), "f"(lo)); return r;
}
__device__ __forceinline__ void mma_bf16(float4& d, uint a0, uint a1, uint a2, uint a3,
                                         uint b0, uint b1) {
    asm volatile("mma.sync.aligned.m16n8k16.row.col.f32.bf16.bf16.f32 "
                 "{%0,%1,%2,%3}, {%4,%5,%6,%7}, {%8,%9}, {%0,%1,%2,%3};"
                 : "+f"(d.x), "+f"(d.y), "+f"(d.z), "+f"(d.w)
                 : "r"(a0), "r"(a1), "r"(a2), "r"(a3), "r"(b0), "r"(b1));
}

// ---------------- scratch ----------------
__device__ float g_mu  [Bz * 32 * Tt];
__device__ float g_rstd[Bz * 32 * Tt];
__device__ float g_kv  [128 * 1024];      // [b*64+s][2C]
__device__ float g_kpT [512 * 128];       // fp32 [c][b*64+s]
__device__ float g_vp  [128 * 512];       // fp32 [b*64+s][c]
__device__ uint  g_kpTb[256 * 128];       // bf16x2 pairs over c
__device__ uint  g_vpb [64 * 512];        // bf16x2 pairs over s
__device__ float g_ksb [128];

// ---------------- seed: g_kv = bkv bcast, g_kpT = 0, g_vp = 0 ----------------
__global__ void seed_kernel(const float* __restrict__ bkv) {
    int i4 = (blockIdx.x * 256 + threadIdx.x) * 4;   // 0..262140
    if (i4 < 131072) {
        float4 bv = *(const float4*)&bkv[i4 & 1023];
        *(float4*)&g_kv[i4] = bv;
    } else if (i4 < 196608) {
        *(float4*)&g_kpT[i4 - 131072] = make_float4(0.f, 0.f, 0.f, 0.f);
    } else {
        *(float4*)&g_vp[i4 - 196608] = make_float4(0.f, 0.f, 0.f, 0.f);
    }
}

// ---------------- pre1: kv gemm (blocks 0-255) + gn stats (blocks 256-1279) ----------------
__global__ void pre1_kernel(const float* __restrict__ x, const float* __restrict__ context,
                            const float* __restrict__ wkv) {
    int bid = blockIdx.x;
    int tid = threadIdx.x;

    if (bid >= 256) {     // ---- groupnorm stats ----
        int idx = bid - 256;                 // b*512 + g*16 + t
        int b = idx >> 9, g = (idx >> 4) & 31, t = idx & 15;
        float s = 0.f, sq = 0.f;
        for (int ci = 0; ci < 16; ci++) {
            const float4* row = (const float4*)(x + (size_t)(((b*Cc + g*16 + ci)*Tt + t)) * HWp);
            float4 v = row[tid];
            s  += v.x + v.y + v.z + v.w;
            sq += v.x*v.x + v.y*v.y + v.z*v.z + v.w*v.w;
        }
        __shared__ float s1[256], s2[256];
        s1[tid] = s; s2[tid] = sq;
        __syncthreads();
        for (int st = 128; st > 0; st >>= 1) {
            if (tid < st) { s1[tid] += s1[tid + st]; s2[tid] += s2[tid + st]; }
            __syncthreads();
        }
        if (tid == 0) {
            const float invN = 1.f / 16384.f;
            float mu  = s1[0] * invN;
            float var = s2[0] * invN - mu * mu;
            g_mu[idx] = mu;
            g_rstd[idx] = rsqrtf(var + EPS);
        }
        return;
    }

    // ---- kv = context @ wkv^T (split-K 8, atomic into seeded g_kv) ----
    __shared__ float As[16][68];
    __shared__ float Bs[16][68];
    int n0 = (bid & 15) * 64;
    int m0 = ((bid >> 4) & 1) * 64;
    int k0base = (bid >> 5) * 128;
    int tx = tid & 15, ty = tid >> 4;

    float acc[4][4];
    #pragma unroll
    for (int i = 0; i < 4; i++)
        #pragma unroll
        for (int j = 0; j < 4; j++) acc[i][j] = 0.f;

    for (int k0 = k0base; k0 < k0base + 128; k0 += 16) {
        {
            int mm = tid >> 2, kb = (tid & 3) << 2;
            float4 av = *(const float4*)&context[(size_t)(m0 + mm) * 1024 + k0 + kb];
            As[kb+0][mm] = av.x; As[kb+1][mm] = av.y;
            As[kb+2][mm] = av.z; As[kb+3][mm] = av.w;
        }
        {
            int nn = tid >> 2, kb = (tid & 3) << 2;
            float4 bv = *(const float4*)&wkv[(size_t)(n0 + nn) * 1024 + k0 + kb];
            Bs[kb+0][nn] = bv.x; Bs[kb+1][nn] = bv.y;
            Bs[kb+2][nn] = bv.z; Bs[kb+3][nn] = bv.w;
        }
        __syncthreads();
        #pragma unroll
        for (int kk = 0; kk < 16; kk++) {
            float4 a4 = *(const float4*)&As[kk][ty << 2];
            float4 b4 = *(const float4*)&Bs[kk][tx << 2];
            float a[4] = {a4.x, a4.y, a4.z, a4.w};
            float bb[4] = {b4.x, b4.y, b4.z, b4.w};
            #pragma unroll
            for (int i = 0; i < 4; i++)
                #pragma unroll
                for (int j = 0; j < 4; j++)
                    acc[i][j] += a[i] * bb[j];
        }
        __syncthreads();
    }
    #pragma unroll
    for (int i = 0; i < 4; i++)
        #pragma unroll
        for (int j = 0; j < 4; j++)
            atomicAdd(&g_kv[(size_t)(m0 + (ty<<2) + i) * 1024 + n0 + (tx<<2) + j], acc[i][j]);
}

// ---------------- proj2: kT (0-127), vp (128-255), ksb (256-259); split-K 8 ----------------
__global__ void proj2_kernel(const float* __restrict__ wq, const float* __restrict__ wo,
                             const float* __restrict__ bq) {
    int bid = blockIdx.x;
    int tid = threadIdx.x;

    if (bid >= 256) {         // ksb: bq . k
        int warp = tid >> 5, lane = tid & 31;
        int base = (bid - 256) * 32 + warp * 4;
        for (int r = 0; r < 4; r++) {
            int row = base + r;
            const float4* kr = (const float4*)&g_kv[(size_t)row * 1024];
            float s = 0.f;
            #pragma unroll
            for (int i = 0; i < 4; i++) {
                float4 kvv = kr[i*32 + lane];
                float4 bqv = *(const float4*)&bq[(i*32 + lane) << 2];
                s += kvv.x*bqv.x + kvv.y*bqv.y + kvv.z*bqv.z + kvv.w*bqv.w;
            }
            #pragma unroll
            for (int off = 16; off > 0; off >>= 1) s += __shfl_xor_sync(FULLMASK, s, off);
            if (lane == 0) g_ksb[row] = s;
        }
        return;
    }

    __shared__ float As[16][68];
    __shared__ float Bs[16][68];
    bool isK = bid < 128;
    int local = bid & 127;
    int n0 = (local & 7) * 64;
    int m0 = ((local >> 3) & 1) * 64;
    int k0base = (local >> 4) * 64;         // split-K 8
    const float* A = isK ? g_kv : (g_kv + 512);
    const float* B = isK ? wq : wo;
    int tx = tid & 15, ty = tid >> 4;

    float acc[4][4];
    #pragma unroll
    for (int i = 0; i < 4; i++)
        #pragma unroll
        for (int j = 0; j < 4; j++) acc[i][j] = 0.f;

    for (int k0 = k0base; k0 < k0base + 64; k0 += 16) {
        {
            int mm = tid >> 2, kb = (tid & 3) << 2;
            float4 av = *(const float4*)&A[(size_t)(m0 + mm) * 1024 + k0 + kb];
            As[kb+0][mm] = av.x; As[kb+1][mm] = av.y;
            As[kb+2][mm] = av.z; As[kb+3][mm] = av.w;
        }
        if (isK) {
            int kk = tid >> 4, nb = (tid & 15) << 2;
            float4 bv = *(const float4*)&B[(size_t)(k0 + kk) * 512 + n0 + nb];
            *(float4*)&Bs[kk][nb] = bv;
        } else {
            int nn = tid >> 2, kb = (tid & 3) << 2;
            float4 bv = *(const float4*)&B[(size_t)(n0 + nn) * 512 + k0 + kb];
            Bs[kb+0][nn] = bv.x; Bs[kb+1][nn] = bv.y;
            Bs[kb+2][nn] = bv.z; Bs[kb+3][nn] = bv.w;
        }
        __syncthreads();
        #pragma unroll
        for (int kk = 0; kk < 16; kk++) {
            float4 a4 = *(const float4*)&As[kk][ty << 2];
            float4 b4 = *(const float4*)&Bs[kk][tx << 2];
            float a[4] = {a4.x, a4.y, a4.z, a4.w};
            float bb[4] = {b4.x, b4.y, b4.z, b4.w};
            #pragma unroll
            for (int i = 0; i < 4; i++)
                #pragma unroll
                for (int j = 0; j < 4; j++)
                    acc[i][j] += a[i] * bb[j];
        }
        __syncthreads();
    }
    #pragma unroll
    for (int i = 0; i < 4; i++)
        #pragma unroll
        for (int j = 0; j < 4; j++) {
            int m = m0 + (ty << 2) + i, n = n0 + (tx << 2) + j;
            if (isK) atomicAdd(&g_kpT[(size_t)n * 128 + m], acc[i][j]);
            else     atomicAdd(&g_vp [(size_t)m * 512 + n], acc[i][j]);
        }
}

// ---------------- cvt: fp32 k'/v' -> packed bf16x2 (vectorized) ----------------
__global__ void cvt_kernel() {
    int j = blockIdx.x * 256 + threadIdx.x;   // 0..16383
    if (j < 8192) {           // kpTb: pair over c, vectorize over s
        int cp = j >> 5, s4 = (j & 31) << 2;
        float4 fa = *(const float4*)&g_kpT[(size_t)(2*cp  ) * 128 + s4];
        float4 fb = *(const float4*)&g_kpT[(size_t)(2*cp+1) * 128 + s4];
        uint4 r;
        r.x = packbf(fa.x, fb.x); r.y = packbf(fa.y, fb.y);
        r.z = packbf(fa.z, fb.z); r.w = packbf(fa.w, fb.w);
        *(uint4*)&g_kpTb[(size_t)cp * 128 + s4] = r;
    } else {                  // vpb: pair over s, vectorize over c
        int j2 = j - 8192;
        int spg = j2 >> 7, c4 = (j2 & 127) << 2;    // spg = b*32 + spair
        int b = spg >> 5, sp = spg & 31;
        float4 fa = *(const float4*)&g_vp[(size_t)(b*64 + 2*sp  ) * 512 + c4];
        float4 fb = *(const float4*)&g_vp[(size_t)(b*64 + 2*sp+1) * 512 + c4];
        uint4 r;
        r.x = packbf(fa.x, fb.x); r.y = packbf(fa.y, fb.y);
        r.z = packbf(fa.z, fb.z); r.w = packbf(fa.w, fb.w);
        *(uint4*)&g_vpb[(size_t)spg * 512 + c4] = r;
    }
}

// ---------------- fused normalize + attention (bf16 mma) + residual ----------------
// block per (b, t, 64-hw tile); 256 threads (8 warps); 48KB dyn smem
__global__ void __launch_bounds__(256, 3) attn_kernel(
    const float* __restrict__ x, const float* __restrict__ gamma,
    const float* __restrict__ beta, const float* __restrict__ bo,
    float* __restrict__ out) {
    extern __shared__ uint shu[];
    float* s_scl = (float*)shu;                     // 512
    float* s_bia = (float*)(shu + 512);             // 512
    uint*  sh_h  = shu + 1024;                      // h chunk 64xHST2 / scores overlay
    __nv_bfloat16* sh_hb = (__nv_bfloat16*)sh_h;
    float* sh_s  = (float*)sh_h;                    // 64 x SSTR fp32 (after score loop)
    uint*  sh_k  = shu + 1024 + 64*HST2;            // kT 64xKST2 / v 32xVSTC
    uint*  sh_w  = shu + 1024 + 64*HST2 + 64*KST2;  // 64 x WST
    __shared__ float sksb[64];

    int bi = blockIdx.x;
    int tile = bi & 15, t = 15 - ((bi >> 4) & 15), b = bi >> 8;
    int hw0 = tile * 64;
    int tid = threadIdx.x;
    const int L   = (t + 1) * 4;
    const int L8  = (L + 7) & ~7;
    const int L16 = (L + 15) & ~15;

    // ---- per-block norm params + score bias ----
    if (tid < 64) sksb[tid] = g_ksb[b * 64 + tid];
    #pragma unroll
    for (int c = tid; c < 512; c += 256) {
        int g = c >> 4;
        float mu = g_mu  [b * 512 + g * 16 + t];
        float rs = g_rstd[b * 512 + g * 16 + t];
        float sc = rs * gamma[c];
        s_scl[c] = sc;
        s_bia[c] = beta[c] - mu * sc;
    }

    // ---- prefetch kT chunk 0 ----
    uint4 pre[4];
    #pragma unroll
    for (int i = 0; i < 4; i++) {
        int idx = i * 256 + tid;
        int cc = idx >> 4, sfu = (idx & 15) << 2;
        if (sfu < L8) pre[i] = *(const uint4*)&g_kpTb[(size_t)cc * 128 + b * 64 + sfu];
    }
    __syncthreads();

    int warp = tid >> 5, lane = tid & 31;
    int grp = lane >> 2, tig = lane & 3;

    // ================= scores: S = h @ kT (streamed h chunks) =================
    {
        int qw = warp >> 1, sw = warp & 1;
        int q0 = qw * 16, sbase = sw * 32;
        float4 C[4];
        #pragma unroll
        for (int nt = 0; nt < 4; nt++) C[nt] = make_float4(0.f, 0.f, 0.f, 0.f);

        for (int ch = 0; ch < 4; ch++) {
            // store prefetched kT chunk
            #pragma unroll
            for (int i = 0; i < 4; i++) {
                int idx = i * 256 + tid;
                int cc = idx >> 4, sfu = (idx & 15) << 2;
                if (sfu < L8) *(uint4*)&sh_k[cc * KST2 + sfu] = pre[i];
            }
            // stage h chunk ch (normalize x slice -> bf16 smem)
            {
                int c0 = ch * 128;
                #pragma unroll
                for (int it = 0; it < 8; it++) {
                    int lin = it * 256 + tid;          // 0..2047
                    int crel = lin >> 4;               // 0..127
                    int hwg = (lin & 15) << 2;         // 0..60
                    int c = c0 + crel;
                    float4 xv = *(const float4*)(x + (size_t)(((b*Cc + c)*Tt + t)) * HWp + hw0 + hwg);
                    float sc = s_scl[c], bi_ = s_bia[c];
                    sh_hb[(hwg+0)*(2*HST2) + crel] = __float2bfloat16(xv.x * sc + bi_);
                    sh_hb[(hwg+1)*(2*HST2) + crel] = __float2bfloat16(xv.y * sc + bi_);
                    sh_hb[(hwg+2)*(2*HST2) + crel] = __float2bfloat16(xv.z * sc + bi_);
                    sh_hb[(hwg+3)*(2*HST2) + crel] = __float2bfloat16(xv.w * sc + bi_);
                }
            }
            __syncthreads();
            // prefetch next (kT ch+1, or v chunk 0)
            if (ch < 3) {
                #pragma unroll
                for (int i = 0; i < 4; i++) {
                    int idx = i * 256 + tid;
                    int cc = idx >> 4, sfu = (idx & 15) << 2;
                    if (sfu < L8)
                        pre[i] = *(const uint4*)&g_kpTb[(size_t)((ch+1)*64 + cc) * 128 + b * 64 + sfu];
                }
            } else {
                #pragma unroll
                for (int i = 0; i < 4; i++) {
                    int idx = i * 256 + tid;
                    int sp = idx >> 5, cu = (idx & 31) << 2;
                    if (sp * 2 < L16)
                        pre[i] = *(const uint4*)&g_vpb[(size_t)(b * 32 + sp) * 512 + cu];
                }
            }
            // mma over this chunk
            #pragma unroll
            for (int k8 = 0; k8 < 8; k8++) {
                int ap = k8 * 8;
                uint a0 = sh_h[(q0+grp  )*HST2 + ap + tig];
                uint a1 = sh_h[(q0+grp+8)*HST2 + ap + tig];
                uint a2 = sh_h[(q0+grp  )*HST2 + ap + tig + 4];
                uint a3 = sh_h[(q0+grp+8)*HST2 + ap + tig + 4];
                #pragma unroll
                for (int nt = 0; nt < 4; nt++) {
                    int s_tile = sbase + nt * 8;
                    if (s_tile < L) {
                        uint b0 = sh_k[(ap+tig  )*KST2 + s_tile + grp];
                        uint b1 = sh_k[(ap+tig+4)*KST2 + s_tile + grp];
                        mma_bf16(C[nt], a0, a1, a2, a3, b0, b1);
                    }
                }
            }
            __syncthreads();
        }
        // epilogue -> fp32 scores (overlays dead h buffer)
        #pragma unroll
        for (int nt = 0; nt < 4; nt++) {
            int s_tile = sbase + nt * 8;
            if (s_tile < L) {
                int s = s_tile + 2 * tig;
                if (s < L) {
                    float kb = sksb[s];
                    sh_s[(q0+grp  )*SSTR + s] = (C[nt].x + kb) * SCALE;
                    sh_s[(q0+grp+8)*SSTR + s] = (C[nt].z + kb) * SCALE;
                }
                if (s + 1 < L) {
                    float kb = sksb[s+1];
                    sh_s[(q0+grp  )*SSTR + s + 1] = (C[nt].y + kb) * SCALE;
                    sh_s[(q0+grp+8)*SSTR + s + 1] = (C[nt].w + kb) * SCALE;
                }
            }
        }
    }
    __syncthreads();

    // ================= softmax (warp = 8 rows) -> packed bf16x2 weights =================
    for (int r = 0; r < 8; r++) {
        int q = warp * 8 + r;
        float v0 = (lane      < L) ? sh_s[q * SSTR + lane     ] : -INFINITY;
        float v1 = (lane + 32 < L) ? sh_s[q * SSTR + lane + 32] : -INFINITY;
        float mx = fmaxf(v0, v1);
        #pragma unroll
        for (int off = 16; off > 0; off >>= 1) mx = fmaxf(mx, __shfl_xor_sync(FULLMASK, mx, off));
        float e0 = __expf(v0 - mx), e1 = __expf(v1 - mx);
        float ds = e0 + e1;
        #pragma unroll
        for (int off = 16; off > 0; off >>= 1) ds += __shfl_xor_sync(FULLMASK, ds, off);
        float inv = 1.f / ds;
        float we = e0 * inv, wo_ = e1 * inv;
        int i0 = (2 * lane) & 31, i1 = (2 * lane + 1) & 31;
        float alo = __shfl_sync(FULLMASK, we,  i0), blo = __shfl_sync(FULLMASK, we,  i1);
        float ahi = __shfl_sync(FULLMASK, wo_, i0), bhi = __shfl_sync(FULLMASK, wo_, i1);
        float wa = lane < 16 ? alo : ahi;
        float wb = lane < 16 ? blo : bhi;
        sh_w[q * WST + lane] = packbf(wa, wb);
    }
    __syncthreads();

    // ================= combine: O = W @ v' + fused residual epilogue =================
    {
        int qw = warp >> 1, cw = warp & 1;
        int q0 = qw * 16;
        const int kmax = L16 >> 4;

        for (int ch = 0; ch < 4; ch++) {
            // store prefetched v chunk
            #pragma unroll
            for (int i = 0; i < 4; i++) {
                int idx = i * 256 + tid;
                int sp = idx >> 5, cu = (idx & 31) << 2;
                if (sp * 2 < L16) *(uint4*)&sh_k[sp * VSTC + cu] = pre[i];
            }
            __syncthreads();
            if (ch < 3) {
                #pragma unroll
                for (int i = 0; i < 4; i++) {
                    int idx = i * 256 + tid;
                    int sp = idx >> 5, cu = (idx & 31) << 2;
                    if (sp * 2 < L16)
                        pre[i] = *(const uint4*)&g_vpb[(size_t)(b * 32 + sp) * 512 + (ch+1)*128 + cu];
                }
            }
            float4 D[8];
            #pragma unroll
            for (int nt = 0; nt < 8; nt++) D[nt] = make_float4(0.f, 0.f, 0.f, 0.f);

            for (int k8 = 0; k8 < kmax; k8++) {
                int sp = k8 * 8;
                uint a0 = sh_w[(q0+grp  )*WST + sp + tig];
                uint a1 = sh_w[(q0+grp+8)*WST + sp + tig];
                uint a2 = sh_w[(q0+grp  )*WST + sp + tig + 4];
                uint a3 = sh_w[(q0+grp+8)*WST + sp + tig + 4];
                #pragma unroll
                for (int nt = 0; nt < 8; nt++) {
                    int n0c = cw * 64 + nt * 8;
                    uint b0 = sh_k[(sp+tig  )*VSTC + n0c + grp];
                    uint b1 = sh_k[(sp+tig+4)*VSTC + n0c + grp];
                    mma_bf16(D[nt], a0, a1, a2, a3, b0, b1);
                }
            }
            // fused epilogue: out = x + o + bo directly from fragments
            int hwA = hw0 + q0 + grp;
            #pragma unroll
            for (int nt = 0; nt < 8; nt++) {
                int c0 = ch*128 + cw*64 + nt*8 + 2*tig;
                float bo0 = bo[c0], bo1 = bo[c0 + 1];
                size_t gA0 = (size_t)(((b*Cc + c0  )*Tt + t)) * HWp + hwA;
                size_t gA1 = (size_t)(((b*Cc + c0+1)*Tt + t)) * HWp + hwA;
                out[gA0]     = x[gA0]     + D[nt].x + bo0;
                out[gA1]     = x[gA1]     + D[nt].y + bo1;
                out[gA0 + 8] = x[gA0 + 8] + D[nt].z + bo0;
                out[gA1 + 8] = x[gA1 + 8] + D[nt].w + bo1;
            }
            __syncthreads();
        }
    }
}

// ---------------- launch ----------------
extern "C" void kernel_launch(void* const* d_in, const int* in_sizes, int n_in,
                              void* d_out, int out_size) {
    const float* x       = (const float*)d_in[0];
    const float* context = (const float*)d_in[1];
    const float* gamma   = (const float*)d_in[2];
    const float* beta    = (const float*)d_in[3];
    const float* wq      = (const float*)d_in[4];
    const float* bq      = (const float*)d_in[5];
    const float* wkv     = (const float*)d_in[6];
    const float* bkv     = (const float*)d_in[7];
    const float* wo      = (const float*)d_in[8];
    const float* bo      = (const float*)d_in[9];
    float* out = (float*)d_out;

    const int SMEM_BYTES = (1024 + 64*HST2 + 64*KST2 + 64*WST) * 4;   // 49152
    cudaFuncSetAttribute(attn_kernel, cudaFuncAttributeMaxDynamicSharedMemorySize, SMEM_BYTES);

    seed_kernel<<<256, 256>>>(bkv);
    pre1_kernel<<<1280, 256>>>(x, context, wkv);
    proj2_kernel<<<260, 256>>>(wq, wo, bq);
    cvt_kernel<<<64, 256>>>();
    attn_kernel<<<Bz * Tt * 16, 256, SMEM_BYTES>>>(x, gamma, beta, bo, out);
}

// round 10
// speedup vs baseline: 1.1220x; 1.1220x over previous
#include <cuda_runtime.h>
#include <cuda_bf16.h>
#include <math.h>

#define Bz   2
#define Cc   512
#define Tt   16
#define HWp  1024
#define EPS  1e-5f
#define SCALE 0.04419417382415922f  // 512^-0.5
#define FULLMASK 0xffffffffu
#define HSTR 260    // h row stride in uints (bf16x2 pairs); 260%32=4 -> conflict-free A frags
#define KST2 72     // kT chunk pair-row stride (uints); 72%32=8 -> conflict-free B frags
#define VST2 136    // v chunk pair-row stride (uints); 136%32=8
#define SSTR 68     // fp32 score row stride
#define WST  36     // packed weight row stride (uints); 36%32=4

typedef unsigned int uint;

// ---------------- helpers ----------------
__device__ __forceinline__ uint packbf(float lo, float hi) {
    uint r; asm("cvt.rn.bf16x2.f32 %0, %1, %2;" : "=r"(r) : "f"(hi), "f"(lo)); return r;
}
__device__ __forceinline__ void mma_bf16(float4& d, uint a0, uint a1, uint a2, uint a3,
                                         uint b0, uint b1) {
    asm volatile("mma.sync.aligned.m16n8k16.row.col.f32.bf16.bf16.f32 "
                 "{%0,%1,%2,%3}, {%4,%5,%6,%7}, {%8,%9}, {%0,%1,%2,%3};"
                 : "+f"(d.x), "+f"(d.y), "+f"(d.z), "+f"(d.w)
                 : "r"(a0), "r"(a1), "r"(a2), "r"(a3), "r"(b0), "r"(b1));
}

// ---------------- scratch ----------------
__device__ float g_mu  [Bz * 32 * Tt];
__device__ float g_rstd[Bz * 32 * Tt];
__device__ float g_kv  [128 * 1024];      // [b*64+s][2C]
__device__ float g_kpT [512 * 128];       // fp32 [c][b*64+s]
__device__ float g_vp  [128 * 512];       // fp32 [b*64+s][c]
__device__ uint  g_kpTb[256 * 128];       // bf16x2 pairs over c
__device__ uint  g_vpb [64 * 512];        // bf16x2 pairs over s
__device__ float g_ksb [128];

// ---------------- seed: g_kv = bkv bcast, g_kpT = 0, g_vp = 0 ----------------
__global__ void seed_kernel(const float* __restrict__ bkv) {
    int i4 = (blockIdx.x * 256 + threadIdx.x) * 4;   // 0..262140
    if (i4 < 131072) {
        float4 bv = *(const float4*)&bkv[i4 & 1023];
        *(float4*)&g_kv[i4] = bv;
    } else if (i4 < 196608) {
        *(float4*)&g_kpT[i4 - 131072] = make_float4(0.f, 0.f, 0.f, 0.f);
    } else {
        *(float4*)&g_vp[i4 - 196608] = make_float4(0.f, 0.f, 0.f, 0.f);
    }
}

// ---------------- pre1: kv gemm (blocks 0-255) + gn stats (blocks 256-1279) ----------------
__global__ void pre1_kernel(const float* __restrict__ x, const float* __restrict__ context,
                            const float* __restrict__ wkv) {
    int bid = blockIdx.x;
    int tid = threadIdx.x;

    if (bid >= 256) {     // ---- groupnorm stats ----
        int idx = bid - 256;                 // b*512 + g*16 + t
        int b = idx >> 9, g = (idx >> 4) & 31, t = idx & 15;
        float s = 0.f, sq = 0.f;
        for (int ci = 0; ci < 16; ci++) {
            const float4* row = (const float4*)(x + (size_t)(((b*Cc + g*16 + ci)*Tt + t)) * HWp);
            float4 v = row[tid];
            s  += v.x + v.y + v.z + v.w;
            sq += v.x*v.x + v.y*v.y + v.z*v.z + v.w*v.w;
        }
        __shared__ float s1[256], s2[256];
        s1[tid] = s; s2[tid] = sq;
        __syncthreads();
        for (int st = 128; st > 0; st >>= 1) {
            if (tid < st) { s1[tid] += s1[tid + st]; s2[tid] += s2[tid + st]; }
            __syncthreads();
        }
        if (tid == 0) {
            const float invN = 1.f / 16384.f;
            float mu  = s1[0] * invN;
            float var = s2[0] * invN - mu * mu;
            g_mu[idx] = mu;
            g_rstd[idx] = rsqrtf(var + EPS);
        }
        return;
    }

    // ---- kv = context @ wkv^T (split-K 8, atomic into seeded g_kv) ----
    __shared__ float As[16][68];
    __shared__ float Bs[16][68];
    int n0 = (bid & 15) * 64;
    int m0 = ((bid >> 4) & 1) * 64;
    int k0base = (bid >> 5) * 128;
    int tx = tid & 15, ty = tid >> 4;

    float acc[4][4];
    #pragma unroll
    for (int i = 0; i < 4; i++)
        #pragma unroll
        for (int j = 0; j < 4; j++) acc[i][j] = 0.f;

    for (int k0 = k0base; k0 < k0base + 128; k0 += 16) {
        {
            int mm = tid >> 2, kb = (tid & 3) << 2;
            float4 av = *(const float4*)&context[(size_t)(m0 + mm) * 1024 + k0 + kb];
            As[kb+0][mm] = av.x; As[kb+1][mm] = av.y;
            As[kb+2][mm] = av.z; As[kb+3][mm] = av.w;
        }
        {
            int nn = tid >> 2, kb = (tid & 3) << 2;
            float4 bv = *(const float4*)&wkv[(size_t)(n0 + nn) * 1024 + k0 + kb];
            Bs[kb+0][nn] = bv.x; Bs[kb+1][nn] = bv.y;
            Bs[kb+2][nn] = bv.z; Bs[kb+3][nn] = bv.w;
        }
        __syncthreads();
        #pragma unroll
        for (int kk = 0; kk < 16; kk++) {
            float4 a4 = *(const float4*)&As[kk][ty << 2];
            float4 b4 = *(const float4*)&Bs[kk][tx << 2];
            float a[4] = {a4.x, a4.y, a4.z, a4.w};
            float bb[4] = {b4.x, b4.y, b4.z, b4.w};
            #pragma unroll
            for (int i = 0; i < 4; i++)
                #pragma unroll
                for (int j = 0; j < 4; j++)
                    acc[i][j] += a[i] * bb[j];
        }
        __syncthreads();
    }
    #pragma unroll
    for (int i = 0; i < 4; i++)
        #pragma unroll
        for (int j = 0; j < 4; j++)
            atomicAdd(&g_kv[(size_t)(m0 + (ty<<2) + i) * 1024 + n0 + (tx<<2) + j], acc[i][j]);
}

// ---------------- proj2: kT (0-127), vp (128-255), ksb (256-259); split-K 8 ----------------
__global__ void proj2_kernel(const float* __restrict__ wq, const float* __restrict__ wo,
                             const float* __restrict__ bq) {
    int bid = blockIdx.x;
    int tid = threadIdx.x;

    if (bid >= 256) {         // ksb: bq . k
        int warp = tid >> 5, lane = tid & 31;
        int base = (bid - 256) * 32 + warp * 4;
        for (int r = 0; r < 4; r++) {
            int row = base + r;
            const float4* kr = (const float4*)&g_kv[(size_t)row * 1024];
            float s = 0.f;
            #pragma unroll
            for (int i = 0; i < 4; i++) {
                float4 kvv = kr[i*32 + lane];
                float4 bqv = *(const float4*)&bq[(i*32 + lane) << 2];
                s += kvv.x*bqv.x + kvv.y*bqv.y + kvv.z*bqv.z + kvv.w*bqv.w;
            }
            #pragma unroll
            for (int off = 16; off > 0; off >>= 1) s += __shfl_xor_sync(FULLMASK, s, off);
            if (lane == 0) g_ksb[row] = s;
        }
        return;
    }

    __shared__ float As[16][68];
    __shared__ float Bs[16][68];
    bool isK = bid < 128;
    int local = bid & 127;
    int n0 = (local & 7) * 64;
    int m0 = ((local >> 3) & 1) * 64;
    int k0base = (local >> 4) * 64;         // split-K 8
    const float* A = isK ? g_kv : (g_kv + 512);
    const float* B = isK ? wq : wo;
    int tx = tid & 15, ty = tid >> 4;

    float acc[4][4];
    #pragma unroll
    for (int i = 0; i < 4; i++)
        #pragma unroll
        for (int j = 0; j < 4; j++) acc[i][j] = 0.f;

    for (int k0 = k0base; k0 < k0base + 64; k0 += 16) {
        {
            int mm = tid >> 2, kb = (tid & 3) << 2;
            float4 av = *(const float4*)&A[(size_t)(m0 + mm) * 1024 + k0 + kb];
            As[kb+0][mm] = av.x; As[kb+1][mm] = av.y;
            As[kb+2][mm] = av.z; As[kb+3][mm] = av.w;
        }
        if (isK) {
            int kk = tid >> 4, nb = (tid & 15) << 2;
            float4 bv = *(const float4*)&B[(size_t)(k0 + kk) * 512 + n0 + nb];
            *(float4*)&Bs[kk][nb] = bv;
        } else {
            int nn = tid >> 2, kb = (tid & 3) << 2;
            float4 bv = *(const float4*)&B[(size_t)(n0 + nn) * 512 + k0 + kb];
            Bs[kb+0][nn] = bv.x; Bs[kb+1][nn] = bv.y;
            Bs[kb+2][nn] = bv.z; Bs[kb+3][nn] = bv.w;
        }
        __syncthreads();
        #pragma unroll
        for (int kk = 0; kk < 16; kk++) {
            float4 a4 = *(const float4*)&As[kk][ty << 2];
            float4 b4 = *(const float4*)&Bs[kk][tx << 2];
            float a[4] = {a4.x, a4.y, a4.z, a4.w};
            float bb[4] = {b4.x, b4.y, b4.z, b4.w};
            #pragma unroll
            for (int i = 0; i < 4; i++)
                #pragma unroll
                for (int j = 0; j < 4; j++)
                    acc[i][j] += a[i] * bb[j];
        }
        __syncthreads();
    }
    #pragma unroll
    for (int i = 0; i < 4; i++)
        #pragma unroll
        for (int j = 0; j < 4; j++) {
            int m = m0 + (ty << 2) + i, n = n0 + (tx << 2) + j;
            if (isK) atomicAdd(&g_kpT[(size_t)n * 128 + m], acc[i][j]);
            else     atomicAdd(&g_vp [(size_t)m * 512 + n], acc[i][j]);
        }
}

// ---------------- cvt: fp32 k'/v' -> packed bf16x2 (vectorized) ----------------
__global__ void cvt_kernel() {
    int j = blockIdx.x * 256 + threadIdx.x;   // 0..16383
    if (j < 8192) {           // kpTb: pair over c, vectorize over s
        int cp = j >> 5, s4 = (j & 31) << 2;
        float4 fa = *(const float4*)&g_kpT[(size_t)(2*cp  ) * 128 + s4];
        float4 fb = *(const float4*)&g_kpT[(size_t)(2*cp+1) * 128 + s4];
        uint4 r;
        r.x = packbf(fa.x, fb.x); r.y = packbf(fa.y, fb.y);
        r.z = packbf(fa.z, fb.z); r.w = packbf(fa.w, fb.w);
        *(uint4*)&g_kpTb[(size_t)cp * 128 + s4] = r;
    } else {                  // vpb: pair over s, vectorize over c
        int j2 = j - 8192;
        int spg = j2 >> 7, c4 = (j2 & 127) << 2;    // spg = b*32 + spair
        int b = spg >> 5, sp = spg & 31;
        float4 fa = *(const float4*)&g_vp[(size_t)(b*64 + 2*sp  ) * 512 + c4];
        float4 fb = *(const float4*)&g_vp[(size_t)(b*64 + 2*sp+1) * 512 + c4];
        uint4 r;
        r.x = packbf(fa.x, fb.x); r.y = packbf(fa.y, fb.y);
        r.z = packbf(fa.z, fb.z); r.w = packbf(fa.w, fb.w);
        *(uint4*)&g_vpb[(size_t)spg * 512 + c4] = r;
    }
}

// ---------------- fused normalize + attention (bf16 mma) + residual ----------------
// block per (b, t, 32-hw tile); 256 threads (8 warps); ~65KB smem -> 3 CTAs/SM
__global__ void __launch_bounds__(256, 3) attn_kernel(
    const float* __restrict__ x, const float* __restrict__ gamma,
    const float* __restrict__ beta, const float* __restrict__ bo,
    float* __restrict__ out) {
    extern __shared__ uint shu[];
    uint* sh_hu = shu;                              // 32 x HSTR  (bf16x2 h pairs over c)
    __nv_bfloat16* sh_hb = (__nv_bfloat16*)shu;     // same, bf16 view (row stride 2*HSTR)
    uint* sh_ku  = shu + 32 * HSTR;                 // kT 64xKST2 / v 32xVST2
    float* sh_sf = (float*)(sh_ku + 64 * KST2);     // 32 x SSTR fp32 scores
    uint* sw_u   = (uint*)(sh_sf + 32 * SSTR);      // 32 x WST packed weights
    __shared__ float sksb[64];

    int bi = blockIdx.x;
    int tile = bi & 31, t = 15 - ((bi >> 5) & 15), b = bi >> 9;
    int hw0 = tile * 32;
    int tid = threadIdx.x;
    const int L   = (t + 1) * 4;
    const int L8  = (L + 7) & ~7;
    const int L16 = (L + 15) & ~15;

    // ---- prefetch kT chunk 0 (packed bf16x2) ----
    uint4 pre[4];
    #pragma unroll
    for (int i = 0; i < 4; i++) {
        int idx = i * 256 + tid;                  // 0..1023
        int cc = idx >> 4, sfu = (idx & 15) << 2;
        if (sfu < L8) pre[i] = *(const uint4*)&g_kpTb[(size_t)cc * 128 + b * 64 + sfu];
    }
    if (tid < 64) sksb[tid] = g_ksb[b * 64 + tid];

    // ---- stage normalized h (bf16) ----
    {
        const float* mub = g_mu   + b * 512 + t;
        const float* rsb = g_rstd + b * 512 + t;
        #pragma unroll
        for (int it = 0; it < 16; it++) {
            int lin = it * 256 + tid;
            int c  = lin >> 3;
            int hw = (lin & 7) << 2;
            float4 xv = *(const float4*)(x + (size_t)(((b*Cc + c)*Tt + t)) * HWp + hw0 + hw);
            int g = c >> 4;
            float scl = rsb[g * 16] * gamma[c];
            float bia = beta[c] - mub[g * 16] * scl;
            sh_hb[(hw+0)*(2*HSTR) + c] = __float2bfloat16(xv.x * scl + bia);
            sh_hb[(hw+1)*(2*HSTR) + c] = __float2bfloat16(xv.y * scl + bia);
            sh_hb[(hw+2)*(2*HSTR) + c] = __float2bfloat16(xv.z * scl + bia);
            sh_hb[(hw+3)*(2*HSTR) + c] = __float2bfloat16(xv.w * scl + bia);
        }
    }
    __syncthreads();

    int warp = tid >> 5, lane = tid & 31;
    int grp = lane >> 2, tig = lane & 3;

    // ================= scores: S = h @ kT (bf16 m16n8k16) =================
    {
        int qw = warp >> 2, sw = warp & 3;
        int q0 = qw * 16;
        int s0a = sw * 16, s0b = sw * 16 + 8;
        bool act0 = s0a < L, act1 = s0b < L;
        float4 C0 = {0,0,0,0}, C1 = {0,0,0,0};

        for (int ch = 0; ch < 4; ch++) {
            // store prefetched kT chunk
            #pragma unroll
            for (int i = 0; i < 4; i++) {
                int idx = i * 256 + tid;
                int cc = idx >> 4, sfu = (idx & 15) << 2;
                if (sfu < L8) *(uint4*)&sh_ku[cc * KST2 + sfu] = pre[i];
            }
            __syncthreads();
            // prefetch next (kT ch+1, or v chunk 0 on last)
            if (ch < 3) {
                #pragma unroll
                for (int i = 0; i < 4; i++) {
                    int idx = i * 256 + tid;
                    int cc = idx >> 4, sfu = (idx & 15) << 2;
                    if (sfu < L8)
                        pre[i] = *(const uint4*)&g_kpTb[(size_t)((ch+1)*64 + cc) * 128 + b * 64 + sfu];
                }
            } else {
                #pragma unroll
                for (int i = 0; i < 4; i++) {
                    int idx = i * 256 + tid;
                    int sp = idx >> 5, cu = (idx & 31) << 2;
                    if (sp * 2 < L16)
                        pre[i] = *(const uint4*)&g_vpb[(size_t)(b * 32 + sp) * 512 + cu];
                }
            }
            if (act0) {
                int pb = ch * 64;               // pair base in sh_h
                #pragma unroll
                for (int k8 = 0; k8 < 8; k8++) {
                    int ap = pb + k8 * 8;
                    uint a0 = sh_hu[(q0+grp  )*HSTR + ap + tig];
                    uint a1 = sh_hu[(q0+grp+8)*HSTR + ap + tig];
                    uint a2 = sh_hu[(q0+grp  )*HSTR + ap + tig + 4];
                    uint a3 = sh_hu[(q0+grp+8)*HSTR + ap + tig + 4];
                    uint b0 = sh_ku[(k8*8+tig  )*KST2 + s0a + grp];
                    uint b1 = sh_ku[(k8*8+tig+4)*KST2 + s0a + grp];
                    mma_bf16(C0, a0, a1, a2, a3, b0, b1);
                    if (act1) {
                        uint b2 = sh_ku[(k8*8+tig  )*KST2 + s0b + grp];
                        uint b3 = sh_ku[(k8*8+tig+4)*KST2 + s0b + grp];
                        mma_bf16(C1, a0, a1, a2, a3, b2, b3);
                    }
                }
            }
            __syncthreads();
        }
        // epilogue -> fp32 scores (+bias, *scale)
        if (act0) {
            int s = s0a + 2 * tig;
            if (s < L) {
                float kb = sksb[s];
                sh_sf[(q0+grp  )*SSTR + s] = (C0.x + kb) * SCALE;
                sh_sf[(q0+grp+8)*SSTR + s] = (C0.z + kb) * SCALE;
            }
            if (s + 1 < L) {
                float kb = sksb[s+1];
                sh_sf[(q0+grp  )*SSTR + s + 1] = (C0.y + kb) * SCALE;
                sh_sf[(q0+grp+8)*SSTR + s + 1] = (C0.w + kb) * SCALE;
            }
            if (act1) {
                int s2 = s0b + 2 * tig;
                if (s2 < L) {
                    float kb = sksb[s2];
                    sh_sf[(q0+grp  )*SSTR + s2] = (C1.x + kb) * SCALE;
                    sh_sf[(q0+grp+8)*SSTR + s2] = (C1.z + kb) * SCALE;
                }
                if (s2 + 1 < L) {
                    float kb = sksb[s2+1];
                    sh_sf[(q0+grp  )*SSTR + s2 + 1] = (C1.y + kb) * SCALE;
                    sh_sf[(q0+grp+8)*SSTR + s2 + 1] = (C1.w + kb) * SCALE;
                }
            }
        }
    }
    __syncthreads();

    // ================= softmax (warp = 4 rows) -> packed bf16x2 weights =================
    for (int r = 0; r < 4; r++) {
        int q = warp * 4 + r;
        float v0 = (lane      < L) ? sh_sf[q * SSTR + lane     ] : -INFINITY;
        float v1 = (lane + 32 < L) ? sh_sf[q * SSTR + lane + 32] : -INFINITY;
        float mx = fmaxf(v0, v1);
        #pragma unroll
        for (int off = 16; off > 0; off >>= 1) mx = fmaxf(mx, __shfl_xor_sync(FULLMASK, mx, off));
        float e0 = __expf(v0 - mx), e1 = __expf(v1 - mx);
        float ds = e0 + e1;
        #pragma unroll
        for (int off = 16; off > 0; off >>= 1) ds += __shfl_xor_sync(FULLMASK, ds, off);
        float inv = 1.f / ds;
        float we = e0 * inv, wo_ = e1 * inv;     // s=lane, s=lane+32 (0 beyond L)
        // gather pair (2p, 2p+1) into lane p
        int i0 = (2 * lane) & 31, i1 = (2 * lane + 1) & 31;
        float alo = __shfl_sync(FULLMASK, we,  i0), blo = __shfl_sync(FULLMASK, we,  i1);
        float ahi = __shfl_sync(FULLMASK, wo_, i0), bhi = __shfl_sync(FULLMASK, wo_, i1);
        float wa = lane < 16 ? alo : ahi;
        float wb = lane < 16 ? blo : bhi;
        sw_u[q * WST + lane] = packbf(wa, wb);
    }
    __syncthreads();

    // ================= combine: O = W @ v' (bf16 m16n8k16), fused epilogue =================
    {
        int qw = warp >> 2, cw = warp & 3;
        int q0 = qw * 16;
        const int kmax = L16 >> 4;

        for (int ch = 0; ch < 4; ch++) {
            // store prefetched v chunk (pair rows up to L16/2: mma reads that far)
            #pragma unroll
            for (int i = 0; i < 4; i++) {
                int idx = i * 256 + tid;
                int sp = idx >> 5, cu = (idx & 31) << 2;
                if (sp * 2 < L16) *(uint4*)&sh_ku[sp * VST2 + cu] = pre[i];
            }
            __syncthreads();
            if (ch < 3) {
                #pragma unroll
                for (int i = 0; i < 4; i++) {
                    int idx = i * 256 + tid;
                    int sp = idx >> 5, cu = (idx & 31) << 2;
                    if (sp * 2 < L16)
                        pre[i] = *(const uint4*)&g_vpb[(size_t)(b * 32 + sp) * 512 + (ch+1)*128 + cu];
                }
            }
            float4 D[4];
            #pragma unroll
            for (int nt = 0; nt < 4; nt++) D[nt] = make_float4(0.f, 0.f, 0.f, 0.f);

            #pragma unroll 4
            for (int k8 = 0; k8 < kmax; k8++) {
                int sp = k8 * 8;
                uint a0 = sw_u[(q0+grp  )*WST + sp + tig];
                uint a1 = sw_u[(q0+grp+8)*WST + sp + tig];
                uint a2 = sw_u[(q0+grp  )*WST + sp + tig + 4];
                uint a3 = sw_u[(q0+grp+8)*WST + sp + tig + 4];
                #pragma unroll
                for (int nt = 0; nt < 4; nt++) {
                    int n0c = cw * 32 + nt * 8;
                    uint b0 = sh_ku[(sp+tig  )*VST2 + n0c + grp];
                    uint b1 = sh_ku[(sp+tig+4)*VST2 + n0c + grp];
                    mma_bf16(D[nt], a0, a1, a2, a3, b0, b1);
                }
            }
            // fused epilogue: out = x + o + bo directly from fragments
            int hwA = hw0 + q0 + grp;
            #pragma unroll
            for (int nt = 0; nt < 4; nt++) {
                int c0 = ch*128 + cw*32 + nt*8 + 2*tig;
                float bo0 = bo[c0], bo1 = bo[c0 + 1];
                size_t gA0 = (size_t)(((b*Cc + c0  )*Tt + t)) * HWp + hwA;
                size_t gA1 = (size_t)(((b*Cc + c0+1)*Tt + t)) * HWp + hwA;
                out[gA0]     = x[gA0]     + D[nt].x + bo0;
                out[gA1]     = x[gA1]     + D[nt].y + bo1;
                out[gA0 + 8] = x[gA0 + 8] + D[nt].z + bo0;   // hw row +8
                out[gA1 + 8] = x[gA1 + 8] + D[nt].w + bo1;
            }
            __syncthreads();
        }
    }
}

// ---------------- launch ----------------
extern "C" void kernel_launch(void* const* d_in, const int* in_sizes, int n_in,
                              void* d_out, int out_size) {
    const float* x       = (const float*)d_in[0];
    const float* context = (const float*)d_in[1];
    const float* gamma   = (const float*)d_in[2];
    const float* beta    = (const float*)d_in[3];
    const float* wq      = (const float*)d_in[4];
    const float* bq      = (const float*)d_in[5];
    const float* wkv     = (const float*)d_in[6];
    const float* bkv     = (const float*)d_in[7];
    const float* wo      = (const float*)d_in[8];
    const float* bo      = (const float*)d_in[9];
    float* out = (float*)d_out;

    const int SMEM_BYTES = (32*HSTR + 64*KST2 + 32*SSTR + 32*WST) * 4;   // 65024
    cudaFuncSetAttribute(attn_kernel, cudaFuncAttributeMaxDynamicSharedMemorySize, SMEM_BYTES);

    seed_kernel<<<256, 256>>>(bkv);
    pre1_kernel<<<1280, 256>>>(x, context, wkv);
    proj2_kernel<<<260, 256>>>(wq, wo, bq);
    cvt_kernel<<<64, 256>>>();
    attn_kernel<<<Bz * Tt * 32, 256, SMEM_BYTES>>>(x, gamma, beta, bo, out);
}

// round 11
// speedup vs baseline: 1.1300x; 1.0071x over previous
#include <cuda_runtime.h>
#include <cuda_bf16.h>
#include <math.h>

#define Bz   2
#define Cc   512
#define Tt   16
#define HWp  1024
#define EPS  1e-5f
#define SCALE 0.04419417382415922f  // 512^-0.5
#define FULLMASK 0xffffffffu
#define HSTR 260    // h row stride in uints (bf16x2 pairs); 260%32=4 -> conflict-free A frags
#define KST2 72     // kT chunk pair-row stride (uints); 72%32=8 -> conflict-free B frags
#define VST2 136    // v chunk pair-row stride (uints); 136%32=8
#define SSTR 68     // fp32 score row stride
#define WST  36     // packed weight row stride (uints); 36%32=4

typedef unsigned int uint;

// ---------------- helpers ----------------
__device__ __forceinline__ uint packbf(float lo, float hi) {
    uint r; asm("cvt.rn.bf16x2.f32 %0, %1, %2;" : "=r"(r) : "f"(hi), "f"(lo)); return r;
}
__device__ __forceinline__ void mma_bf16(float4& d, uint a0, uint a1, uint a2, uint a3,
                                         uint b0, uint b1) {
    asm volatile("mma.sync.aligned.m16n8k16.row.col.f32.bf16.bf16.f32 "
                 "{%0,%1,%2,%3}, {%4,%5,%6,%7}, {%8,%9}, {%0,%1,%2,%3};"
                 : "+f"(d.x), "+f"(d.y), "+f"(d.z), "+f"(d.w)
                 : "r"(a0), "r"(a1), "r"(a2), "r"(a3), "r"(b0), "r"(b1));
}

// ---------------- scratch ----------------
__device__ float g_mu  [Bz * 32 * Tt];
__device__ float g_rstd[Bz * 32 * Tt];
__device__ float g_kv  [128 * 1024];      // [b*64+s][2C]
__device__ float g_kpT [512 * 128];       // fp32 [c][b*64+s]
__device__ float g_vp  [128 * 512];       // fp32 [b*64+s][c]
__device__ uint  g_kpTb[256 * 128];       // bf16x2 pairs over c
__device__ uint  g_vpb [64 * 512];        // bf16x2 pairs over s
__device__ float g_ksb [128];

// ---------------- seed: g_kv = bkv bcast, g_kpT = 0, g_vp = 0 ----------------
__global__ void seed_kernel(const float* __restrict__ bkv) {
    int i4 = (blockIdx.x * 256 + threadIdx.x) * 4;   // 0..262140
    if (i4 < 131072) {
        float4 bv = *(const float4*)&bkv[i4 & 1023];
        *(float4*)&g_kv[i4] = bv;
    } else if (i4 < 196608) {
        *(float4*)&g_kpT[i4 - 131072] = make_float4(0.f, 0.f, 0.f, 0.f);
    } else {
        *(float4*)&g_vp[i4 - 196608] = make_float4(0.f, 0.f, 0.f, 0.f);
    }
}

// ---------------- pre1: kv gemm (blocks 0-255) + gn stats (blocks 256-1279) ----------------
__global__ void pre1_kernel(const float* __restrict__ x, const float* __restrict__ context,
                            const float* __restrict__ wkv) {
    int bid = blockIdx.x;
    int tid = threadIdx.x;

    if (bid >= 256) {     // ---- groupnorm stats ----
        int idx = bid - 256;                 // b*512 + g*16 + t
        int b = idx >> 9, g = (idx >> 4) & 31, t = idx & 15;
        float s = 0.f, sq = 0.f;
        for (int ci = 0; ci < 16; ci++) {
            const float4* row = (const float4*)(x + (size_t)(((b*Cc + g*16 + ci)*Tt + t)) * HWp);
            float4 v = row[tid];
            s  += v.x + v.y + v.z + v.w;
            sq += v.x*v.x + v.y*v.y + v.z*v.z + v.w*v.w;
        }
        __shared__ float s1[256], s2[256];
        s1[tid] = s; s2[tid] = sq;
        __syncthreads();
        for (int st = 128; st > 0; st >>= 1) {
            if (tid < st) { s1[tid] += s1[tid + st]; s2[tid] += s2[tid + st]; }
            __syncthreads();
        }
        if (tid == 0) {
            const float invN = 1.f / 16384.f;
            float mu  = s1[0] * invN;
            float var = s2[0] * invN - mu * mu;
            g_mu[idx] = mu;
            g_rstd[idx] = rsqrtf(var + EPS);
        }
        return;
    }

    // ---- kv = context @ wkv^T (split-K 8, atomic into seeded g_kv) ----
    __shared__ float As[16][68];
    __shared__ float Bs[16][68];
    int n0 = (bid & 15) * 64;
    int m0 = ((bid >> 4) & 1) * 64;
    int k0base = (bid >> 5) * 128;
    int tx = tid & 15, ty = tid >> 4;

    float acc[4][4];
    #pragma unroll
    for (int i = 0; i < 4; i++)
        #pragma unroll
        for (int j = 0; j < 4; j++) acc[i][j] = 0.f;

    for (int k0 = k0base; k0 < k0base + 128; k0 += 16) {
        {
            int mm = tid >> 2, kb = (tid & 3) << 2;
            float4 av = *(const float4*)&context[(size_t)(m0 + mm) * 1024 + k0 + kb];
            As[kb+0][mm] = av.x; As[kb+1][mm] = av.y;
            As[kb+2][mm] = av.z; As[kb+3][mm] = av.w;
        }
        {
            int nn = tid >> 2, kb = (tid & 3) << 2;
            float4 bv = *(const float4*)&wkv[(size_t)(n0 + nn) * 1024 + k0 + kb];
            Bs[kb+0][nn] = bv.x; Bs[kb+1][nn] = bv.y;
            Bs[kb+2][nn] = bv.z; Bs[kb+3][nn] = bv.w;
        }
        __syncthreads();
        #pragma unroll
        for (int kk = 0; kk < 16; kk++) {
            float4 a4 = *(const float4*)&As[kk][ty << 2];
            float4 b4 = *(const float4*)&Bs[kk][tx << 2];
            float a[4] = {a4.x, a4.y, a4.z, a4.w};
            float bb[4] = {b4.x, b4.y, b4.z, b4.w};
            #pragma unroll
            for (int i = 0; i < 4; i++)
                #pragma unroll
                for (int j = 0; j < 4; j++)
                    acc[i][j] += a[i] * bb[j];
        }
        __syncthreads();
    }
    #pragma unroll
    for (int i = 0; i < 4; i++)
        #pragma unroll
        for (int j = 0; j < 4; j++)
            atomicAdd(&g_kv[(size_t)(m0 + (ty<<2) + i) * 1024 + n0 + (tx<<2) + j], acc[i][j]);
}

// ---------------- proj2: kT (0-127), vp (128-255), ksb (256-259); split-K 8 ----------------
__global__ void proj2_kernel(const float* __restrict__ wq, const float* __restrict__ wo,
                             const float* __restrict__ bq) {
    int bid = blockIdx.x;
    int tid = threadIdx.x;

    if (bid >= 256) {         // ksb: bq . k
        int warp = tid >> 5, lane = tid & 31;
        int base = (bid - 256) * 32 + warp * 4;
        for (int r = 0; r < 4; r++) {
            int row = base + r;
            const float4* kr = (const float4*)&g_kv[(size_t)row * 1024];
            float s = 0.f;
            #pragma unroll
            for (int i = 0; i < 4; i++) {
                float4 kvv = kr[i*32 + lane];
                float4 bqv = *(const float4*)&bq[(i*32 + lane) << 2];
                s += kvv.x*bqv.x + kvv.y*bqv.y + kvv.z*bqv.z + kvv.w*bqv.w;
            }
            #pragma unroll
            for (int off = 16; off > 0; off >>= 1) s += __shfl_xor_sync(FULLMASK, s, off);
            if (lane == 0) g_ksb[row] = s;
        }
        return;
    }

    __shared__ float As[16][68];
    __shared__ float Bs[16][68];
    bool isK = bid < 128;
    int local = bid & 127;
    int n0 = (local & 7) * 64;
    int m0 = ((local >> 3) & 1) * 64;
    int k0base = (local >> 4) * 64;         // split-K 8
    const float* A = isK ? g_kv : (g_kv + 512);
    const float* B = isK ? wq : wo;
    int tx = tid & 15, ty = tid >> 4;

    float acc[4][4];
    #pragma unroll
    for (int i = 0; i < 4; i++)
        #pragma unroll
        for (int j = 0; j < 4; j++) acc[i][j] = 0.f;

    for (int k0 = k0base; k0 < k0base + 64; k0 += 16) {
        {
            int mm = tid >> 2, kb = (tid & 3) << 2;
            float4 av = *(const float4*)&A[(size_t)(m0 + mm) * 1024 + k0 + kb];
            As[kb+0][mm] = av.x; As[kb+1][mm] = av.y;
            As[kb+2][mm] = av.z; As[kb+3][mm] = av.w;
        }
        if (isK) {
            int kk = tid >> 4, nb = (tid & 15) << 2;
            float4 bv = *(const float4*)&B[(size_t)(k0 + kk) * 512 + n0 + nb];
            *(float4*)&Bs[kk][nb] = bv;
        } else {
            int nn = tid >> 2, kb = (tid & 3) << 2;
            float4 bv = *(const float4*)&B[(size_t)(n0 + nn) * 512 + k0 + kb];
            Bs[kb+0][nn] = bv.x; Bs[kb+1][nn] = bv.y;
            Bs[kb+2][nn] = bv.z; Bs[kb+3][nn] = bv.w;
        }
        __syncthreads();
        #pragma unroll
        for (int kk = 0; kk < 16; kk++) {
            float4 a4 = *(const float4*)&As[kk][ty << 2];
            float4 b4 = *(const float4*)&Bs[kk][tx << 2];
            float a[4] = {a4.x, a4.y, a4.z, a4.w};
            float bb[4] = {b4.x, b4.y, b4.z, b4.w};
            #pragma unroll
            for (int i = 0; i < 4; i++)
                #pragma unroll
                for (int j = 0; j < 4; j++)
                    acc[i][j] += a[i] * bb[j];
        }
        __syncthreads();
    }
    #pragma unroll
    for (int i = 0; i < 4; i++)
        #pragma unroll
        for (int j = 0; j < 4; j++) {
            int m = m0 + (ty << 2) + i, n = n0 + (tx << 2) + j;
            if (isK) atomicAdd(&g_kpT[(size_t)n * 128 + m], acc[i][j]);
            else     atomicAdd(&g_vp [(size_t)m * 512 + n], acc[i][j]);
        }
}

// ---------------- cvt: fp32 k'/v' -> packed bf16x2 (vectorized) ----------------
__global__ void cvt_kernel() {
    int j = blockIdx.x * 256 + threadIdx.x;   // 0..16383
    if (j < 8192) {           // kpTb: pair over c, vectorize over s
        int cp = j >> 5, s4 = (j & 31) << 2;
        float4 fa = *(const float4*)&g_kpT[(size_t)(2*cp  ) * 128 + s4];
        float4 fb = *(const float4*)&g_kpT[(size_t)(2*cp+1) * 128 + s4];
        uint4 r;
        r.x = packbf(fa.x, fb.x); r.y = packbf(fa.y, fb.y);
        r.z = packbf(fa.z, fb.z); r.w = packbf(fa.w, fb.w);
        *(uint4*)&g_kpTb[(size_t)cp * 128 + s4] = r;
    } else {                  // vpb: pair over s, vectorize over c
        int j2 = j - 8192;
        int spg = j2 >> 7, c4 = (j2 & 127) << 2;    // spg = b*32 + spair
        int b = spg >> 5, sp = spg & 31;
        float4 fa = *(const float4*)&g_vp[(size_t)(b*64 + 2*sp  ) * 512 + c4];
        float4 fb = *(const float4*)&g_vp[(size_t)(b*64 + 2*sp+1) * 512 + c4];
        uint4 r;
        r.x = packbf(fa.x, fb.x); r.y = packbf(fa.y, fb.y);
        r.z = packbf(fa.z, fb.z); r.w = packbf(fa.w, fb.w);
        *(uint4*)&g_vpb[(size_t)spg * 512 + c4] = r;
    }
}

// ---------------- fused normalize + attention (bf16 mma) + residual ----------------
// block per (b, t, 32-hw tile); 256 threads (8 warps); ~65KB smem -> 3 CTAs/SM
__global__ void __launch_bounds__(256, 3) attn_kernel(
    const float* __restrict__ x, const float* __restrict__ gamma,
    const float* __restrict__ beta, const float* __restrict__ bo,
    float* __restrict__ out) {
    extern __shared__ uint shu[];
    uint* sh_hu = shu;                              // 32 x HSTR  (bf16x2 h pairs over c)
    __nv_bfloat16* sh_hb = (__nv_bfloat16*)shu;     // same, bf16 view (row stride 2*HSTR)
    uint* sh_ku  = shu + 32 * HSTR;                 // kT 64xKST2 / v 32xVST2
    float* sh_sf = (float*)(sh_ku + 64 * KST2);     // 32 x SSTR fp32 scores
    uint* sw_u   = (uint*)(sh_sf + 32 * SSTR);      // 32 x WST packed weights
    __shared__ float sksb[64];

    int bi = blockIdx.x;
    int tile = bi & 31, t = 15 - ((bi >> 5) & 15), b = bi >> 9;
    int hw0 = tile * 32;
    int tid = threadIdx.x;
    const int L   = (t + 1) * 4;
    const int L8  = (L + 7) & ~7;
    const int L16 = (L + 15) & ~15;

    // ---- prefetch kT chunk 0 (packed bf16x2) ----
    uint4 pre[4];
    #pragma unroll
    for (int i = 0; i < 4; i++) {
        int idx = i * 256 + tid;                  // 0..1023
        int cc = idx >> 4, sfu = (idx & 15) << 2;
        if (sfu < L8) pre[i] = *(const uint4*)&g_kpTb[(size_t)cc * 128 + b * 64 + sfu];
    }
    if (tid < 64) sksb[tid] = g_ksb[b * 64 + tid];

    // ---- stage normalized h (bf16) ----
    {
        const float* mub = g_mu   + b * 512 + t;
        const float* rsb = g_rstd + b * 512 + t;
        #pragma unroll
        for (int it = 0; it < 16; it++) {
            int lin = it * 256 + tid;
            int c  = lin >> 3;
            int hw = (lin & 7) << 2;
            float4 xv = *(const float4*)(x + (size_t)(((b*Cc + c)*Tt + t)) * HWp + hw0 + hw);
            int g = c >> 4;
            float scl = rsb[g * 16] * gamma[c];
            float bia = beta[c] - mub[g * 16] * scl;
            sh_hb[(hw+0)*(2*HSTR) + c] = __float2bfloat16(xv.x * scl + bia);
            sh_hb[(hw+1)*(2*HSTR) + c] = __float2bfloat16(xv.y * scl + bia);
            sh_hb[(hw+2)*(2*HSTR) + c] = __float2bfloat16(xv.z * scl + bia);
            sh_hb[(hw+3)*(2*HSTR) + c] = __float2bfloat16(xv.w * scl + bia);
        }
    }
    __syncthreads();

    int warp = tid >> 5, lane = tid & 31;
    int grp = lane >> 2, tig = lane & 3;

    // ================= scores: S = h @ kT (bf16 m16n8k16) =================
    {
        int qw = warp >> 2, sw = warp & 3;
        int q0 = qw * 16;
        int s0a = sw * 16, s0b = sw * 16 + 8;
        bool act0 = s0a < L, act1 = s0b < L;
        float4 C0 = {0,0,0,0}, C1 = {0,0,0,0};

        for (int ch = 0; ch < 4; ch++) {
            // store prefetched kT chunk
            #pragma unroll
            for (int i = 0; i < 4; i++) {
                int idx = i * 256 + tid;
                int cc = idx >> 4, sfu = (idx & 15) << 2;
                if (sfu < L8) *(uint4*)&sh_ku[cc * KST2 + sfu] = pre[i];
            }
            __syncthreads();
            // prefetch next (kT ch+1, or v chunk 0 on last)
            if (ch < 3) {
                #pragma unroll
                for (int i = 0; i < 4; i++) {
                    int idx = i * 256 + tid;
                    int cc = idx >> 4, sfu = (idx & 15) << 2;
                    if (sfu < L8)
                        pre[i] = *(const uint4*)&g_kpTb[(size_t)((ch+1)*64 + cc) * 128 + b * 64 + sfu];
                }
            } else {
                #pragma unroll
                for (int i = 0; i < 4; i++) {
                    int idx = i * 256 + tid;
                    int sp = idx >> 5, cu = (idx & 31) << 2;
                    if (sp * 2 < L16)
                        pre[i] = *(const uint4*)&g_vpb[(size_t)(b * 32 + sp) * 512 + cu];
                }
            }
            if (act0) {
                int pb = ch * 64;               // pair base in sh_h
                #pragma unroll
                for (int k8 = 0; k8 < 8; k8++) {
                    int ap = pb + k8 * 8;
                    uint a0 = sh_hu[(q0+grp  )*HSTR + ap + tig];
                    uint a1 = sh_hu[(q0+grp+8)*HSTR + ap + tig];
                    uint a2 = sh_hu[(q0+grp  )*HSTR + ap + tig + 4];
                    uint a3 = sh_hu[(q0+grp+8)*HSTR + ap + tig + 4];
                    uint b0 = sh_ku[(k8*8+tig  )*KST2 + s0a + grp];
                    uint b1 = sh_ku[(k8*8+tig+4)*KST2 + s0a + grp];
                    mma_bf16(C0, a0, a1, a2, a3, b0, b1);
                    if (act1) {
                        uint b2 = sh_ku[(k8*8+tig  )*KST2 + s0b + grp];
                        uint b3 = sh_ku[(k8*8+tig+4)*KST2 + s0b + grp];
                        mma_bf16(C1, a0, a1, a2, a3, b2, b3);
                    }
                }
            }
            __syncthreads();
        }
        // epilogue -> fp32 scores (+bias, *scale)
        if (act0) {
            int s = s0a + 2 * tig;
            if (s < L) {
                float kb = sksb[s];
                sh_sf[(q0+grp  )*SSTR + s] = (C0.x + kb) * SCALE;
                sh_sf[(q0+grp+8)*SSTR + s] = (C0.z + kb) * SCALE;
            }
            if (s + 1 < L) {
                float kb = sksb[s+1];
                sh_sf[(q0+grp  )*SSTR + s + 1] = (C0.y + kb) * SCALE;
                sh_sf[(q0+grp+8)*SSTR + s + 1] = (C0.w + kb) * SCALE;
            }
            if (act1) {
                int s2 = s0b + 2 * tig;
                if (s2 < L) {
                    float kb = sksb[s2];
                    sh_sf[(q0+grp  )*SSTR + s2] = (C1.x + kb) * SCALE;
                    sh_sf[(q0+grp+8)*SSTR + s2] = (C1.z + kb) * SCALE;
                }
                if (s2 + 1 < L) {
                    float kb = sksb[s2+1];
                    sh_sf[(q0+grp  )*SSTR + s2 + 1] = (C1.y + kb) * SCALE;
                    sh_sf[(q0+grp+8)*SSTR + s2 + 1] = (C1.w + kb) * SCALE;
                }
            }
        }
    }
    __syncthreads();

    // ================= softmax (warp = 4 rows) -> packed bf16x2 weights =================
    for (int r = 0; r < 4; r++) {
        int q = warp * 4 + r;
        float v0 = (lane      < L) ? sh_sf[q * SSTR + lane     ] : -INFINITY;
        float v1 = (lane + 32 < L) ? sh_sf[q * SSTR + lane + 32] : -INFINITY;
        float mx = fmaxf(v0, v1);
        #pragma unroll
        for (int off = 16; off > 0; off >>= 1) mx = fmaxf(mx, __shfl_xor_sync(FULLMASK, mx, off));
        float e0 = __expf(v0 - mx), e1 = __expf(v1 - mx);
        float ds = e0 + e1;
        #pragma unroll
        for (int off = 16; off > 0; off >>= 1) ds += __shfl_xor_sync(FULLMASK, ds, off);
        float inv = 1.f / ds;
        float we = e0 * inv, wo_ = e1 * inv;     // s=lane, s=lane+32 (0 beyond L)
        // gather pair (2p, 2p+1) into lane p
        int i0 = (2 * lane) & 31, i1 = (2 * lane + 1) & 31;
        float alo = __shfl_sync(FULLMASK, we,  i0), blo = __shfl_sync(FULLMASK, we,  i1);
        float ahi = __shfl_sync(FULLMASK, wo_, i0), bhi = __shfl_sync(FULLMASK, wo_, i1);
        float wa = lane < 16 ? alo : ahi;
        float wb = lane < 16 ? blo : bhi;
        sw_u[q * WST + lane] = packbf(wa, wb);
    }
    __syncthreads();

    // ================= combine: O = W @ v' (bf16 m16n8k16), fused epilogue =================
    {
        int qw = warp >> 2, cw = warp & 3;
        int q0 = qw * 16;
        const int kmax = L16 >> 4;

        for (int ch = 0; ch < 4; ch++) {
            // store prefetched v chunk (pair rows up to L16/2: mma reads that far)
            #pragma unroll
            for (int i = 0; i < 4; i++) {
                int idx = i * 256 + tid;
                int sp = idx >> 5, cu = (idx & 31) << 2;
                if (sp * 2 < L16) *(uint4*)&sh_ku[sp * VST2 + cu] = pre[i];
            }
            __syncthreads();
            if (ch < 3) {
                #pragma unroll
                for (int i = 0; i < 4; i++) {
                    int idx = i * 256 + tid;
                    int sp = idx >> 5, cu = (idx & 31) << 2;
                    if (sp * 2 < L16)
                        pre[i] = *(const uint4*)&g_vpb[(size_t)(b * 32 + sp) * 512 + (ch+1)*128 + cu];
                }
            }
            float4 D[4];
            #pragma unroll
            for (int nt = 0; nt < 4; nt++) D[nt] = make_float4(0.f, 0.f, 0.f, 0.f);

            #pragma unroll 4
            for (int k8 = 0; k8 < kmax; k8++) {
                int sp = k8 * 8;
                uint a0 = sw_u[(q0+grp  )*WST + sp + tig];
                uint a1 = sw_u[(q0+grp+8)*WST + sp + tig];
                uint a2 = sw_u[(q0+grp  )*WST + sp + tig + 4];
                uint a3 = sw_u[(q0+grp+8)*WST + sp + tig + 4];
                #pragma unroll
                for (int nt = 0; nt < 4; nt++) {
                    int n0c = cw * 32 + nt * 8;
                    uint b0 = sh_ku[(sp+tig  )*VST2 + n0c + grp];
                    uint b1 = sh_ku[(sp+tig+4)*VST2 + n0c + grp];
                    mma_bf16(D[nt], a0, a1, a2, a3, b0, b1);
                }
            }
            // fused epilogue: out = x + o + bo directly from fragments
            int hwA = hw0 + q0 + grp;
            #pragma unroll
            for (int nt = 0; nt < 4; nt++) {
                int c0 = ch*128 + cw*32 + nt*8 + 2*tig;
                float bo0 = bo[c0], bo1 = bo[c0 + 1];
                size_t gA0 = (size_t)(((b*Cc + c0  )*Tt + t)) * HWp + hwA;
                size_t gA1 = (size_t)(((b*Cc + c0+1)*Tt + t)) * HWp + hwA;
                out[gA0]     = x[gA0]     + D[nt].x + bo0;
                out[gA1]     = x[gA1]     + D[nt].y + bo1;
                out[gA0 + 8] = x[gA0 + 8] + D[nt].z + bo0;   // hw row +8
                out[gA1 + 8] = x[gA1 + 8] + D[nt].w + bo1;
            }
            __syncthreads();
        }
    }
}

// ---------------- launch ----------------
extern "C" void kernel_launch(void* const* d_in, const int* in_sizes, int n_in,
                              void* d_out, int out_size) {
    const float* x       = (const float*)d_in[0];
    const float* context = (const float*)d_in[1];
    const float* gamma   = (const float*)d_in[2];
    const float* beta    = (const float*)d_in[3];
    const float* wq      = (const float*)d_in[4];
    const float* bq      = (const float*)d_in[5];
    const float* wkv     = (const float*)d_in[6];
    const float* bkv     = (const float*)d_in[7];
    const float* wo      = (const float*)d_in[8];
    const float* bo      = (const float*)d_in[9];
    float* out = (float*)d_out;

    const int SMEM_BYTES = (32*HSTR + 64*KST2 + 32*SSTR + 32*WST) * 4;   // 65024
    cudaFuncSetAttribute(attn_kernel, cudaFuncAttributeMaxDynamicSharedMemorySize, SMEM_BYTES);

    seed_kernel<<<256, 256>>>(bkv);
    pre1_kernel<<<1280, 256>>>(x, context, wkv);
    proj2_kernel<<<260, 256>>>(wq, wo, bq);
    cvt_kernel<<<64, 256>>>();
    attn_kernel<<<Bz * Tt * 32, 256, SMEM_BYTES>>>(x, gamma, beta, bo, out);
}

// round 12
// speedup vs baseline: 1.2998x; 1.1503x over previous
#include <cuda_runtime.h>
#include <cuda_bf16.h>
#include <math.h>

#define Bz   2
#define Cc   512
#define Tt   16
#define HWp  1024
#define EPS  1e-5f
#define SCALE 0.04419417382415922f  // 512^-0.5
#define FULLMASK 0xffffffffu
#define SSTR 68     // fp32 score row stride
#define WST  36     // packed weight row stride (uints)

typedef unsigned int uint;

// ---------------- helpers ----------------
__device__ __forceinline__ uint packbf(float lo, float hi) {
    uint r; asm("cvt.rn.bf16x2.f32 %0, %1, %2;" : "=r"(r) : "f"(hi), "f"(lo)); return r;
}
__device__ __forceinline__ void mma_bf16(float4& d, uint a0, uint a1, uint a2, uint a3,
                                         uint b0, uint b1) {
    asm volatile("mma.sync.aligned.m16n8k16.row.col.f32.bf16.bf16.f32 "
                 "{%0,%1,%2,%3}, {%4,%5,%6,%7}, {%8,%9}, {%0,%1,%2,%3};"
                 : "+f"(d.x), "+f"(d.y), "+f"(d.z), "+f"(d.w)
                 : "r"(a0), "r"(a1), "r"(a2), "r"(a3), "r"(b0), "r"(b1));
}

// ---------------- scratch ----------------
__device__ float g_mu  [Bz * 32 * Tt];
__device__ float g_rstd[Bz * 32 * Tt];
__device__ float g_kv  [128 * 1024];      // [b*64+s][2C]
__device__ float g_kpT [512 * 128];       // fp32 [c][b*64+s]
__device__ float g_vp  [128 * 512];       // fp32 [b*64+s][c]
__device__ uint2 g_kf  [16384];           // score B frags: [b][st(8)][k8(32)][lane(32)]
__device__ uint2 g_vf  [16384];           // combine B frags: [b][k8s(4)][ct(64)][lane(32)]
__device__ float g_ksb [128];

// ---------------- seed: g_kv = bkv bcast, g_kpT = 0, g_vp = 0 ----------------
__global__ void seed_kernel(const float* __restrict__ bkv) {
    int i4 = (blockIdx.x * 256 + threadIdx.x) * 4;   // 0..262140
    if (i4 < 131072) {
        float4 bv = *(const float4*)&bkv[i4 & 1023];
        *(float4*)&g_kv[i4] = bv;
    } else if (i4 < 196608) {
        *(float4*)&g_kpT[i4 - 131072] = make_float4(0.f, 0.f, 0.f, 0.f);
    } else {
        *(float4*)&g_vp[i4 - 196608] = make_float4(0.f, 0.f, 0.f, 0.f);
    }
}

// ---------------- pre1: kv gemm (blocks 0-255) + gn stats (blocks 256-1279) ----------------
__global__ void pre1_kernel(const float* __restrict__ x, const float* __restrict__ context,
                            const float* __restrict__ wkv) {
    int bid = blockIdx.x;
    int tid = threadIdx.x;

    if (bid >= 256) {     // ---- groupnorm stats ----
        int idx = bid - 256;                 // b*512 + g*16 + t
        int b = idx >> 9, g = (idx >> 4) & 31, t = idx & 15;
        float s = 0.f, sq = 0.f;
        for (int ci = 0; ci < 16; ci++) {
            const float4* row = (const float4*)(x + (size_t)(((b*Cc + g*16 + ci)*Tt + t)) * HWp);
            float4 v = row[tid];
            s  += v.x + v.y + v.z + v.w;
            sq += v.x*v.x + v.y*v.y + v.z*v.z + v.w*v.w;
        }
        __shared__ float s1[256], s2[256];
        s1[tid] = s; s2[tid] = sq;
        __syncthreads();
        for (int st = 128; st > 0; st >>= 1) {
            if (tid < st) { s1[tid] += s1[tid + st]; s2[tid] += s2[tid + st]; }
            __syncthreads();
        }
        if (tid == 0) {
            const float invN = 1.f / 16384.f;
            float mu  = s1[0] * invN;
            float var = s2[0] * invN - mu * mu;
            g_mu[idx] = mu;
            g_rstd[idx] = rsqrtf(var + EPS);
        }
        return;
    }

    // ---- kv = context @ wkv^T (split-K 8, atomic into seeded g_kv) ----
    __shared__ float As[16][68];
    __shared__ float Bs[16][68];
    int n0 = (bid & 15) * 64;
    int m0 = ((bid >> 4) & 1) * 64;
    int k0base = (bid >> 5) * 128;
    int tx = tid & 15, ty = tid >> 4;

    float acc[4][4];
    #pragma unroll
    for (int i = 0; i < 4; i++)
        #pragma unroll
        for (int j = 0; j < 4; j++) acc[i][j] = 0.f;

    for (int k0 = k0base; k0 < k0base + 128; k0 += 16) {
        {
            int mm = tid >> 2, kb = (tid & 3) << 2;
            float4 av = *(const float4*)&context[(size_t)(m0 + mm) * 1024 + k0 + kb];
            As[kb+0][mm] = av.x; As[kb+1][mm] = av.y;
            As[kb+2][mm] = av.z; As[kb+3][mm] = av.w;
        }
        {
            int nn = tid >> 2, kb = (tid & 3) << 2;
            float4 bv = *(const float4*)&wkv[(size_t)(n0 + nn) * 1024 + k0 + kb];
            Bs[kb+0][nn] = bv.x; Bs[kb+1][nn] = bv.y;
            Bs[kb+2][nn] = bv.z; Bs[kb+3][nn] = bv.w;
        }
        __syncthreads();
        #pragma unroll
        for (int kk = 0; kk < 16; kk++) {
            float4 a4 = *(const float4*)&As[kk][ty << 2];
            float4 b4 = *(const float4*)&Bs[kk][tx << 2];
            float a[4] = {a4.x, a4.y, a4.z, a4.w};
            float bb[4] = {b4.x, b4.y, b4.z, b4.w};
            #pragma unroll
            for (int i = 0; i < 4; i++)
                #pragma unroll
                for (int j = 0; j < 4; j++)
                    acc[i][j] += a[i] * bb[j];
        }
        __syncthreads();
    }
    #pragma unroll
    for (int i = 0; i < 4; i++)
        #pragma unroll
        for (int j = 0; j < 4; j++)
            atomicAdd(&g_kv[(size_t)(m0 + (ty<<2) + i) * 1024 + n0 + (tx<<2) + j], acc[i][j]);
}

// ---------------- proj2: kT (0-127), vp (128-255), ksb (256-259); split-K 8 ----------------
__global__ void proj2_kernel(const float* __restrict__ wq, const float* __restrict__ wo,
                             const float* __restrict__ bq) {
    int bid = blockIdx.x;
    int tid = threadIdx.x;

    if (bid >= 256) {         // ksb: bq . k
        int warp = tid >> 5, lane = tid & 31;
        int base = (bid - 256) * 32 + warp * 4;
        for (int r = 0; r < 4; r++) {
            int row = base + r;
            const float4* kr = (const float4*)&g_kv[(size_t)row * 1024];
            float s = 0.f;
            #pragma unroll
            for (int i = 0; i < 4; i++) {
                float4 kvv = kr[i*32 + lane];
                float4 bqv = *(const float4*)&bq[(i*32 + lane) << 2];
                s += kvv.x*bqv.x + kvv.y*bqv.y + kvv.z*bqv.z + kvv.w*bqv.w;
            }
            #pragma unroll
            for (int off = 16; off > 0; off >>= 1) s += __shfl_xor_sync(FULLMASK, s, off);
            if (lane == 0) g_ksb[row] = s;
        }
        return;
    }

    __shared__ float As[16][68];
    __shared__ float Bs[16][68];
    bool isK = bid < 128;
    int local = bid & 127;
    int n0 = (local & 7) * 64;
    int m0 = ((local >> 3) & 1) * 64;
    int k0base = (local >> 4) * 64;         // split-K 8
    const float* A = isK ? g_kv : (g_kv + 512);
    const float* B = isK ? wq : wo;
    int tx = tid & 15, ty = tid >> 4;

    float acc[4][4];
    #pragma unroll
    for (int i = 0; i < 4; i++)
        #pragma unroll
        for (int j = 0; j < 4; j++) acc[i][j] = 0.f;

    for (int k0 = k0base; k0 < k0base + 64; k0 += 16) {
        {
            int mm = tid >> 2, kb = (tid & 3) << 2;
            float4 av = *(const float4*)&A[(size_t)(m0 + mm) * 1024 + k0 + kb];
            As[kb+0][mm] = av.x; As[kb+1][mm] = av.y;
            As[kb+2][mm] = av.z; As[kb+3][mm] = av.w;
        }
        if (isK) {
            int kk = tid >> 4, nb = (tid & 15) << 2;
            float4 bv = *(const float4*)&B[(size_t)(k0 + kk) * 512 + n0 + nb];
            *(float4*)&Bs[kk][nb] = bv;
        } else {
            int nn = tid >> 2, kb = (tid & 3) << 2;
            float4 bv = *(const float4*)&B[(size_t)(n0 + nn) * 512 + k0 + kb];
            Bs[kb+0][nn] = bv.x; Bs[kb+1][nn] = bv.y;
            Bs[kb+2][nn] = bv.z; Bs[kb+3][nn] = bv.w;
        }
        __syncthreads();
        #pragma unroll
        for (int kk = 0; kk < 16; kk++) {
            float4 a4 = *(const float4*)&As[kk][ty << 2];
            float4 b4 = *(const float4*)&Bs[kk][tx << 2];
            float a[4] = {a4.x, a4.y, a4.z, a4.w};
            float bb[4] = {b4.x, b4.y, b4.z, b4.w};
            #pragma unroll
            for (int i = 0; i < 4; i++)
                #pragma unroll
                for (int j = 0; j < 4; j++)
                    acc[i][j] += a[i] * bb[j];
        }
        __syncthreads();
    }
    #pragma unroll
    for (int i = 0; i < 4; i++)
        #pragma unroll
        for (int j = 0; j < 4; j++) {
            int m = m0 + (ty << 2) + i, n = n0 + (tx << 2) + j;
            if (isK) atomicAdd(&g_kpT[(size_t)n * 128 + m], acc[i][j]);
            else     atomicAdd(&g_vp [(size_t)m * 512 + n], acc[i][j]);
        }
}

// ---------------- cvt: fp32 k'/v' -> mma-fragment-order bf16x2 ----------------
__global__ void cvt_kernel() {
    int j = blockIdx.x * 256 + threadIdx.x;   // 0..32767
    if (j < 16384) {          // score B frags: [b][st][k8][lane]
        int lane = j & 31;
        int k8   = (j >> 5) & 31;
        int st   = (j >> 10) & 7;
        int b    = (j >> 13) & 1;
        int tig = lane & 3, grp = lane >> 2;
        int scol = b * 64 + st * 8 + grp;
        int c00 = k8 * 16 + tig * 2;
        int c10 = c00 + 8;
        uint2 r;
        r.x = packbf(g_kpT[(size_t)c00 * 128 + scol], g_kpT[(size_t)(c00+1) * 128 + scol]);
        r.y = packbf(g_kpT[(size_t)c10 * 128 + scol], g_kpT[(size_t)(c10+1) * 128 + scol]);
        g_kf[j] = r;
    } else {                  // combine B frags: [b][k8s][ct][lane]
        int j2 = j - 16384;
        int lane = j2 & 31;
        int ct   = (j2 >> 5) & 63;
        int k8s  = (j2 >> 11) & 3;
        int b    = (j2 >> 13) & 1;
        int tig = lane & 3, grp = lane >> 2;
        int c = ct * 8 + grp;
        int srow = b * 64 + k8s * 16 + tig * 2;
        uint2 r;
        r.x = packbf(g_vp[(size_t)srow     * 512 + c], g_vp[(size_t)(srow+1) * 512 + c]);
        r.y = packbf(g_vp[(size_t)(srow+8) * 512 + c], g_vp[(size_t)(srow+9) * 512 + c]);
        g_vf[j2] = r;
    }
}

// ---------------- fused normalize + attention (bf16 mma, B from global frags) ----------------
// block per (b, t, 32-hw tile); 256 threads (8 warps); ~49KB dyn smem
__global__ void __launch_bounds__(256) attn_kernel(
    const float* __restrict__ x, const float* __restrict__ gamma,
    const float* __restrict__ beta, const float* __restrict__ bo,
    float* __restrict__ out) {
    extern __shared__ uint shu[];
    float* s_scl  = (float*)shu;                     // 512
    float* s_bia  = (float*)(shu + 512);             // 512
    uint*  frag_h = shu + 1024;                      // 8192: [qw(2)][k8(32)][lane(32)][reg(4)]
    float* sh_sf  = (float*)(shu + 1024 + 8192);     // 32 x SSTR fp32 scores
    uint*  sw_u   = shu + 1024 + 8192 + 32*SSTR;     // 32 x WST packed weights
    __shared__ float sksb[64];

    int bi = blockIdx.x;
    int tile = bi & 31, t = 15 - ((bi >> 5) & 15), b = bi >> 9;
    int hw0 = tile * 32;
    int tid = threadIdx.x;
    const int L   = (t + 1) * 4;
    const int L16 = (L + 15) & ~15;

    // ---- per-block norm params + score bias ----
    if (tid < 64) sksb[tid] = g_ksb[b * 64 + tid];
    #pragma unroll
    for (int c = tid; c < 512; c += 256) {
        int g = c >> 4;
        float mu = g_mu  [b * 512 + g * 16 + t];
        float rs = g_rstd[b * 512 + g * 16 + t];
        float sc = rs * gamma[c];
        s_scl[c] = sc;
        s_bia[c] = beta[c] - mu * sc;
    }
    __syncthreads();

    // ---- stage normalized h into fragment-major layout ----
    #pragma unroll
    for (int it = 0; it < 8; it++) {
        int lin = it * 256 + tid;            // 0..2047
        int cpair = lin >> 3;                // 0..255
        int hwq = (lin & 7) << 2;            // 0,4,..,28
        int c0 = cpair * 2;
        const float* xp = x + ((size_t)(b * 512 + c0) * 16 + t) * 1024 + hw0 + hwq;
        float4 x0 = *(const float4*)xp;
        float4 x1 = *(const float4*)(xp + 16384);    // c0+1 row
        float sc0 = s_scl[c0],   bi0 = s_bia[c0];
        float sc1 = s_scl[c0+1], bi1 = s_bia[c0+1];
        int k8 = cpair >> 3;
        int cp7 = cpair & 7;
        int tig_ = cp7 & 3;
        int regc = (cp7 >> 2) << 1;          // 0 or 2
        float xa[4] = {x0.x, x0.y, x0.z, x0.w};
        float xb[4] = {x1.x, x1.y, x1.z, x1.w};
        #pragma unroll
        for (int i = 0; i < 4; i++) {
            int hw = hwq + i;
            int qw = hw >> 4, r = hw & 15;
            int lane2 = (r & 7) * 4 + tig_;
            int reg = regc + (r >> 3);
            frag_h[(qw * 32 + k8) * 128 + lane2 * 4 + reg] =
                packbf(xa[i] * sc0 + bi0, xb[i] * sc1 + bi1);
        }
    }
    __syncthreads();

    int warp = tid >> 5, lane = tid & 31;
    int grp = lane >> 2, tig = lane & 3;

    // ================= scores: warp = one s-tile (8 s), both q-tiles =================
    {
        int st = warp;
        if (st * 8 < L) {
            float4 C0 = {0,0,0,0}, C1 = {0,0,0,0};
            const uint2* kf = g_kf + ((size_t)(b * 8 + st) * 32) * 32 + lane;
            #pragma unroll 8
            for (int k8 = 0; k8 < 32; k8++) {
                uint4 A0 = *(const uint4*)&frag_h[k8 * 128 + lane * 4];
                uint4 A1 = *(const uint4*)&frag_h[(32 + k8) * 128 + lane * 4];
                uint2 Bv = kf[k8 * 32];
                mma_bf16(C0, A0.x, A0.y, A0.z, A0.w, Bv.x, Bv.y);
                mma_bf16(C1, A1.x, A1.y, A1.z, A1.w, Bv.x, Bv.y);
            }
            int s = st * 8 + 2 * tig;
            if (s < L) {
                float kb = sksb[s];
                sh_sf[ grp      * SSTR + s] = (C0.x + kb) * SCALE;
                sh_sf[(grp + 8) * SSTR + s] = (C0.z + kb) * SCALE;
                sh_sf[(16 + grp) * SSTR + s] = (C1.x + kb) * SCALE;
                sh_sf[(24 + grp) * SSTR + s] = (C1.z + kb) * SCALE;
            }
            if (s + 1 < L) {
                float kb = sksb[s + 1];
                sh_sf[ grp      * SSTR + s + 1] = (C0.y + kb) * SCALE;
                sh_sf[(grp + 8) * SSTR + s + 1] = (C0.w + kb) * SCALE;
                sh_sf[(16 + grp) * SSTR + s + 1] = (C1.y + kb) * SCALE;
                sh_sf[(24 + grp) * SSTR + s + 1] = (C1.w + kb) * SCALE;
            }
        }
    }
    __syncthreads();

    // ================= softmax (warp = 4 rows) -> packed bf16x2 weights =================
    for (int r = 0; r < 4; r++) {
        int q = warp * 4 + r;
        float v0 = (lane      < L) ? sh_sf[q * SSTR + lane     ] : -INFINITY;
        float v1 = (lane + 32 < L) ? sh_sf[q * SSTR + lane + 32] : -INFINITY;
        float mx = fmaxf(v0, v1);
        #pragma unroll
        for (int off = 16; off > 0; off >>= 1) mx = fmaxf(mx, __shfl_xor_sync(FULLMASK, mx, off));
        float e0 = __expf(v0 - mx), e1 = __expf(v1 - mx);
        float ds = e0 + e1;
        #pragma unroll
        for (int off = 16; off > 0; off >>= 1) ds += __shfl_xor_sync(FULLMASK, ds, off);
        float inv = 1.f / ds;
        float we = e0 * inv, wo_ = e1 * inv;     // s=lane, s=lane+32 (0 beyond L)
        int i0 = (2 * lane) & 31, i1 = (2 * lane + 1) & 31;
        float alo = __shfl_sync(FULLMASK, we,  i0), blo = __shfl_sync(FULLMASK, we,  i1);
        float ahi = __shfl_sync(FULLMASK, wo_, i0), bhi = __shfl_sync(FULLMASK, wo_, i1);
        float wa = lane < 16 ? alo : ahi;
        float wb = lane < 16 ? blo : bhi;
        sw_u[q * WST + lane] = packbf(wa, wb);
    }
    __syncthreads();

    // ================= combine: warp owns 64 c cols, both q-tiles; fused epilogue =================
    {
        const int kmax = L16 >> 4;
        int w = warp;
        #pragma unroll
        for (int ch2 = 0; ch2 < 2; ch2++) {
            float4 D0[4], D1[4];
            #pragma unroll
            for (int nt = 0; nt < 4; nt++) {
                D0[nt] = make_float4(0.f, 0.f, 0.f, 0.f);
                D1[nt] = make_float4(0.f, 0.f, 0.f, 0.f);
            }
            for (int k8s = 0; k8s < kmax; k8s++) {
                int sp = k8s * 8;
                uint a00 = sw_u[ grp       * WST + sp + tig];
                uint a01 = sw_u[(grp + 8)  * WST + sp + tig];
                uint a02 = sw_u[ grp       * WST + sp + tig + 4];
                uint a03 = sw_u[(grp + 8)  * WST + sp + tig + 4];
                uint a10 = sw_u[(16 + grp) * WST + sp + tig];
                uint a11 = sw_u[(24 + grp) * WST + sp + tig];
                uint a12 = sw_u[(16 + grp) * WST + sp + tig + 4];
                uint a13 = sw_u[(24 + grp) * WST + sp + tig + 4];
                #pragma unroll
                for (int nt = 0; nt < 4; nt++) {
                    int ct = w * 8 + ch2 * 4 + nt;
                    uint2 Bv = g_vf[((size_t)(b * 4 + k8s) * 64 + ct) * 32 + lane];
                    mma_bf16(D0[nt], a00, a01, a02, a03, Bv.x, Bv.y);
                    mma_bf16(D1[nt], a10, a11, a12, a13, Bv.x, Bv.y);
                }
            }
            // fused epilogue: out = x + o + bo
            #pragma unroll
            for (int nt = 0; nt < 4; nt++) {
                int ct = w * 8 + ch2 * 4 + nt;
                int c0 = ct * 8 + 2 * tig;
                float bo0 = bo[c0], bo1 = bo[c0 + 1];
                size_t gA0 = ((size_t)(b * 512 + c0) * 16 + t) * 1024 + hw0 + grp;
                size_t gA1 = gA0 + 16384;     // c0+1 row
                out[gA0]      = x[gA0]      + D0[nt].x + bo0;
                out[gA1]      = x[gA1]      + D0[nt].y + bo1;
                out[gA0 + 8]  = x[gA0 + 8]  + D0[nt].z + bo0;
                out[gA1 + 8]  = x[gA1 + 8]  + D0[nt].w + bo1;
                size_t gB0 = gA0 + 16;        // q-tile 1: hw +16
                size_t gB1 = gA1 + 16;
                out[gB0]      = x[gB0]      + D1[nt].x + bo0;
                out[gB1]      = x[gB1]      + D1[nt].y + bo1;
                out[gB0 + 8]  = x[gB0 + 8]  + D1[nt].z + bo0;
                out[gB1 + 8]  = x[gB1 + 8]  + D1[nt].w + bo1;
            }
        }
    }
}

// ---------------- launch ----------------
extern "C" void kernel_launch(void* const* d_in, const int* in_sizes, int n_in,
                              void* d_out, int out_size) {
    const float* x       = (const float*)d_in[0];
    const float* context = (const float*)d_in[1];
    const float* gamma   = (const float*)d_in[2];
    const float* beta    = (const float*)d_in[3];
    const float* wq      = (const float*)d_in[4];
    const float* bq      = (const float*)d_in[5];
    const float* wkv     = (const float*)d_in[6];
    const float* bkv     = (const float*)d_in[7];
    const float* wo      = (const float*)d_in[8];
    const float* bo      = (const float*)d_in[9];
    float* out = (float*)d_out;

    const int SMEM_BYTES = (1024 + 8192 + 32*SSTR + 32*WST) * 4;   // 50176
    cudaFuncSetAttribute(attn_kernel, cudaFuncAttributeMaxDynamicSharedMemorySize, SMEM_BYTES);

    seed_kernel<<<256, 256>>>(bkv);
    pre1_kernel<<<1280, 256>>>(x, context, wkv);
    proj2_kernel<<<260, 256>>>(wq, wo, bq);
    cvt_kernel<<<128, 256>>>();
    attn_kernel<<<Bz * Tt * 32, 256, SMEM_BYTES>>>(x, gamma, beta, bo, out);
}